// round 13
// baseline (speedup 1.0000x reference)
#include <cuda_runtime.h>

#define T_STEPS 2000
#define NB      1024
#define NMUL    16
#define NLANES  (NB * NMUL)      // 16384
#define NTH     128              // 4 warps -> SMSPs 0..3 (1 warp/SMSP)
#define NBLK    128              // scan: 128*128 = 16384 threads
#define PF      4                // forcing prefetch depth

// 131 MB scratch for raw Qsim (t, b, m) — module-static, no runtime alloc
__device__ float g_qs[(size_t)T_STEPS * NLANES];

__device__ __forceinline__ float fast_lg2(float a) {
    float r;
    asm("lg2.approx.f32 %0, %1;" : "=f"(r) : "f"(a));
    return r;
}
__device__ __forceinline__ float fast_ex2(float a) {
    float r;
    asm("ex2.approx.f32 %0, %1;" : "=f"(r) : "f"(a));
    return r;
}

// ---------------- Kernel 1: the sequential HBV scan (recurrence only) --------
__global__ void __launch_bounds__(NTH, 1)
hbv_scan(const float* __restrict__ x,      // (T, B, 3)
         const float* __restrict__ ps)     // (B, 288)
{
    const int tid = blockIdx.x * NTH + threadIdx.x;   // 0..16383
    const int m   = tid & (NMUL - 1);
    const int b   = tid >> 4;

    const float* pb = ps + b * 288 + m;

    const float BETA   = 1.0f   + pb[0*16]  * 5.0f;
    const float FC     = 50.0f  + pb[1*16]  * 950.0f;
    const float K0     = 0.05f  + pb[2*16]  * 0.85f;
    const float K1     = 0.01f  + pb[3*16]  * 0.49f;
    const float K2     = 0.001f + pb[4*16]  * 0.199f;
    const float LP     = 0.2f   + pb[5*16]  * 0.8f;
    const float PERC   =          pb[6*16]  * 10.0f;
    const float UZL    =          pb[7*16]  * 100.0f;
    const float TT     = -2.5f  + pb[8*16]  * 5.0f;
    const float CFMAX  = 0.5f   + pb[9*16]  * 9.5f;
    const float CFR    =          pb[10*16] * 0.1f;
    const float CWH    =          pb[11*16] * 0.2f;
    const float BETAET = 0.3f   + pb[12*16] * 4.7f;
    const float Cpar   =          pb[13*16];

    const float invFC    = 1.0f / FC;
    const float bLP      = BETAET * fast_lg2(1.0f / LP);
    const float epsF     = 1e-5f * invFC;
    const float CFRCFMAX = CFR * CFMAX;
    const float CinvFC   = Cpar * invFC;
    const float oneK1    = 1.0f - K1;
    const float oneK2    = 1.0f - K2;
    const float opCWH    = 1.0f + CWH;

    // state (y = SM/FC normalized; invariant y in (0,1])
    float SP  = 1e-5f, MW = 1e-5f, SUZ = 1e-5f, SLZ = 1e-5f;
    float y   = epsF;

    // forcing prefetch ring
    const float* xr = x + (size_t)b * 3;
    float Pf[PF], Tf[PF], Ef[PF];
#pragma unroll
    for (int k = 0; k < PF; ++k) {
        const float* xp = xr + (size_t)k * (NB * 3);
        Pf[k] = __ldg(xp + 0);
        Tf[k] = __ldg(xp + 1);
        Ef[k] = __ldg(xp + 2);
    }

    float* qo = g_qs + tid;

#pragma unroll 1
    for (int c = 0; c < T_STEPS / 8; ++c) {
#pragma unroll
        for (int j = 0; j < 8; ++j) {
            const int t = c * 8 + j;
            const int s4 = j & (PF - 1);
            const float Pm = Pf[s4], Tc = Tf[s4], PE = Ef[s4];
            {
                const int tn = (t + PF < T_STEPS) ? (t + PF) : (T_STEPS - 1);
                const float* xp = xr + (size_t)tn * (NB * 3);
                Pf[s4] = __ldg(xp + 0);
                Tf[s4] = __ldg(xp + 1);
                Ef[s4] = __ldg(xp + 2);
            }

            // snow (reassociated so tosoil avoids SP/MW tail serialization)
            const float rain = (Tc >= TT) ? Pm : 0.0f;
            const float snow = Pm - rain;
            const float m0 = fmaxf(CFMAX * (Tc - TT), 0.0f);
            const float r0 = fmaxf(CFRCFMAX * (TT - Tc), 0.0f);
            const float SP1 = SP + snow;
            const float melt = fminf(m0, SP1);
            const float MW1 = MW + melt;
            const float refreeze = fminf(r0, MW1);
            const float A  = fmaf(-CWH, SP1, MW1);
            const float A2 = fmaf(CWH, melt, A);
            const float g  = fmaf(-opCWH, refreeze, A2);
            const float tosoil = fmaxf(g, 0.0f);
            SP = SP1 - melt + refreeze;
            MW = MW1 - refreeze - tosoil;

            // soil (y = SM/FC), chain-minimized (yp-form)
            const float inr  = rain + tosoil;
            const float inrF = inr * invFC;
            const float yp   = y + inrF;                 // parallel with lg2
            const float sv   = SLZ * CinvFC;
            const float oms  = 1.0f - sv;
            const float sw   = fast_ex2(BETA * fast_lg2(y));  // <=1 invariant
            const float recharge = inr * sw;
            const float y1 = fmaf(-inrF, sw, yp);        // y + inrF*(1-sw)
            const float excess = fmaxf(y1 - 1.0f, 0.0f) * FC;
            const float y2 = fminf(y1, 1.0f);
            const float y3 = fmaf(y2, oms, sv);          // capillary fused
            const float cap = SLZ * fmaxf(fmaf(-Cpar, y1, Cpar), 0.0f);
            SLZ -= cap;
            const float ef  = fast_ex2(fmaf(fast_lg2(y3), BETAET, bLP));
            const float PEF = PE * invFC;
            const float Kfl = fmaxf(y3 - PEF, epsF);     // clamp off-chain
            y = fmaxf(fmaf(-PEF, ef, y3), Kfl);

            // response
            const float SUZ1 = SUZ + recharge + excess;
            const float SUZ2 = fmaxf(SUZ1 - PERC, 0.0f);
            const float PERCv = SUZ1 - SUZ2;
            const float tq  = fmaxf(SUZ2 - UZL, 0.0f);
            const float Q0  = K0 * tq;
            const float SUZ3 = fmaf(-K0, tq, SUZ2);
            const float Q1  = K1 * SUZ3;
            SUZ = oneK1 * SUZ3;
            const float SLZ1 = SLZ + PERCv;
            const float Q2  = K2 * SLZ1;
            SLZ = oneK2 * SLZ1;

            qo[(size_t)t * NLANES] = Q0 + Q1 + Q2;   // STG, fire-and-forget
        }
    }
}

// ---------------- Kernel 2: routing FIR + m-mean (massively parallel) --------
#define TCH 125    // t per block; 16 * 125 = 2000
#define QPAD 142   // row stride: even/odd half-lanes hit disjoint bank halves

__global__ void __launch_bounds__(256, 4)
hbv_conv(const float* __restrict__ ps,     // (B, 288)
         float* __restrict__ out)          // (T, B)
{
    __shared__ float ws[NMUL][16];         // normalized taps (incl. 1/16 mean)
    __shared__ float qs[NMUL][QPAD];       // transposed Q tile [m][t_local]

    const int b   = blockIdx.x;
    const int t0  = blockIdx.y * TCH;
    const int tid = threadIdx.x;

    // weights: 240 threads compute one tap each (gammaln cancels)
    if (tid < 240) {
        const int mm = tid / 15, k = tid % 15;
        const float aa = fmaxf(ps[b * 288 + 256 + mm] * 2.9f, 0.0f) + 0.1f;
        const float th = fmaxf(ps[b * 288 + 272 + mm] * 6.5f, 0.0f) + 0.5f;
        const float tk = (float)k + 0.5f;
        ws[mm][k] = expf((aa - 1.0f) * logf(tk) - tk / th);
    }
    __syncthreads();
    if (tid < NMUL) {
        float s = 0.0f;
#pragma unroll
        for (int k = 0; k < 15; ++k) s += ws[tid][k];
        const float inv = 0.0625f / s;      // fold mean over 16 members
#pragma unroll
        for (int k = 0; k < 15; ++k) ws[tid][k] *= inv;
    }

    // load Q tile: t in [t0-14, t0+124], zero-pad t<0
    for (int idx = tid; idx < (TCH + 14) * NMUL; idx += 256) {
        const int tl = idx >> 4, mm = idx & 15;
        const int tg = t0 - 14 + tl;
        qs[mm][tl] = (tg >= 0)
                   ? g_qs[(size_t)tg * NLANES + b * NMUL + mm] : 0.0f;
    }
    __syncthreads();

    // compute: 2 threads per output t (one per m-half), pair-reduce via shfl
    {
        int tsub = tid >> 1;
        const bool live = (tsub < TCH);
        if (tsub >= TCH) tsub = TCH - 1;             // keep all lanes in shfl
        const int mb = (tid & 1) * 8;
        float a0 = 0.0f, a1 = 0.0f;
#pragma unroll
        for (int mm = 0; mm < 8; ++mm) {
            const float* qr = &qs[mb + mm][tsub];    // taps at qr[14-k]
            const float* wr = ws[mb + mm];
#pragma unroll
            for (int k = 0; k < 15; k += 2) {
                a0 = fmaf(wr[k], qr[14 - k], a0);
                if (k + 1 < 15) a1 = fmaf(wr[k + 1], qr[13 - k], a1);
            }
        }
        float acc = a0 + a1;
        acc += __shfl_xor_sync(0xffffffffu, acc, 1);
        if (live && (tid & 1) == 0)
            out[(size_t)(t0 + tsub) * NB + b] = acc;
    }
}

extern "C" void kernel_launch(void* const* d_in, const int* in_sizes, int n_in,
                              void* d_out, int out_size)
{
    const float* x  = (const float*)d_in[0];
    const float* ps = (const float*)d_in[1];
    if (n_in >= 2 && in_sizes[0] == NB * 288) {  // swapped order
        x  = (const float*)d_in[1];
        ps = (const float*)d_in[0];
    }
    float* out = (float*)d_out;
    hbv_scan<<<NBLK, NTH>>>(x, ps);
    hbv_conv<<<dim3(NB, T_STEPS / TCH), 256>>>(ps, out);
}

// round 14
// speedup vs baseline: 2.7333x; 2.7333x over previous
#include <cuda_runtime.h>

#define T_STEPS 2000
#define NB      1024
#define NMUL    16
#define NTH     256   // warps 0-3: scan (1/SMSP); warps 4-7: conv helpers
#define NBLK    128   // 128 blocks * 4 scan warps * 32 lanes = 16384 lanes
#define CH      16    // steps per chunk (= conv ring size)
#define NCHUNK  (T_STEPS / CH)   // 125
#define PF      4     // forcing prefetch depth
#define CSTR    336   // red[] cell stride: %32==16 -> conflict-free

__device__ __forceinline__ float fast_lg2(float a) {
    float r;
    asm("lg2.approx.f32 %0, %1;" : "=f"(r) : "f"(a));
    return r;
}
__device__ __forceinline__ float fast_ex2(float a) {
    float r;
    asm("ex2.approx.f32 %0, %1;" : "=f"(r) : "f"(a));
    return r;
}
__device__ __forceinline__ void bar64(int id) {
    asm volatile("bar.sync %0, %1;" :: "r"(id), "r"(64) : "memory");
}

__global__ void __launch_bounds__(NTH, 1)
hbv_kernel(const float* __restrict__ x,      // (T, B, 3)
           const float* __restrict__ ps,     // (B, 288)
           float* __restrict__ out)          // (T, B)
{
    // double-buffered Q staging: [buf][pair][j][lane]
    __shared__ float qbuf[2][4][CH][32];
    // helper-side transpose buffer: [pair][cell*CSTR + j*20 + m]
    __shared__ float red[4][2 * CSTR];

    const int w_id = threadIdx.x >> 5;
    const int lane = threadIdx.x & 31;
    const int m    = lane & (NMUL - 1);
    const int cell = lane >> 4;
    const int pair = w_id & 3;             // SMSP id; scan w and helper w+4 share
    const int gwarp = blockIdx.x * 4 + pair;
    const int b     = gwarp * 2 + cell;
    const int b0    = gwarp * 2;

    if (w_id < 4) {
        // ================= SCAN WARP: recurrence only =================
        const float* pb = ps + b * 288 + m;

        const float BETA   = 1.0f   + pb[0*16]  * 5.0f;
        const float FC     = 50.0f  + pb[1*16]  * 950.0f;
        const float K0     = 0.05f  + pb[2*16]  * 0.85f;
        const float K1     = 0.01f  + pb[3*16]  * 0.49f;
        const float K2     = 0.001f + pb[4*16]  * 0.199f;
        const float LP     = 0.2f   + pb[5*16]  * 0.8f;
        const float PERC   =          pb[6*16]  * 10.0f;
        const float UZL    =          pb[7*16]  * 100.0f;
        const float TT     = -2.5f  + pb[8*16]  * 5.0f;
        const float CFMAX  = 0.5f   + pb[9*16]  * 9.5f;
        const float CFR    =          pb[10*16] * 0.1f;
        const float CWH    =          pb[11*16] * 0.2f;
        const float BETAET = 0.3f   + pb[12*16] * 4.7f;
        const float Cpar   =          pb[13*16];

        const float invFC    = 1.0f / FC;
        const float bLP      = BETAET * fast_lg2(1.0f / LP);
        const float epsF     = 1e-5f * invFC;
        const float CFRCFMAX = CFR * CFMAX;
        const float CinvFC   = Cpar * invFC;
        const float oneK1    = 1.0f - K1;
        const float oneK2    = 1.0f - K2;
        const float opCWH    = 1.0f + CWH;

        float SP = 1e-5f, MW = 1e-5f, SUZ = 1e-5f, SLZ = 1e-5f;
        float y  = epsF;

        const float* xr = x + (size_t)b * 3;
        float Pf[PF], Tf[PF], Ef[PF];
#pragma unroll
        for (int k = 0; k < PF; ++k) {
            const float* xp = xr + (size_t)k * (NB * 3);
            Pf[k] = __ldg(xp + 0);
            Tf[k] = __ldg(xp + 1);
            Ef[k] = __ldg(xp + 2);
        }

#pragma unroll 1
        for (int c = 0; c < NCHUNK; ++c) {
            float* qb = &qbuf[c & 1][pair][0][lane];
#pragma unroll
            for (int j = 0; j < CH; ++j) {
                const int t = c * CH + j;
                const int s4 = j & (PF - 1);
                const float Pm = Pf[s4], Tc = Tf[s4], PE = Ef[s4];
                {
                    const int tn = (t + PF < T_STEPS) ? (t + PF) : (T_STEPS - 1);
                    const float* xp = xr + (size_t)tn * (NB * 3);
                    Pf[s4] = __ldg(xp + 0);
                    Tf[s4] = __ldg(xp + 1);
                    Ef[s4] = __ldg(xp + 2);
                }

                // snow (reassociated: tosoil off the SP/MW tails)
                const float rain = (Tc >= TT) ? Pm : 0.0f;
                const float snow = Pm - rain;
                const float m0 = fmaxf(CFMAX * (Tc - TT), 0.0f);
                const float r0 = fmaxf(CFRCFMAX * (TT - Tc), 0.0f);
                const float SP1 = SP + snow;
                const float melt = fminf(m0, SP1);
                const float MW1 = MW + melt;
                const float refreeze = fminf(r0, MW1);
                const float A  = fmaf(-CWH, SP1, MW1);
                const float A2 = fmaf(CWH, melt, A);
                const float g  = fmaf(-opCWH, refreeze, A2);
                const float tosoil = fmaxf(g, 0.0f);
                SP = SP1 - melt + refreeze;
                MW = MW1 - refreeze - tosoil;

                // soil (y = SM/FC in (0,1]), chain-minimized
                const float inr  = rain + tosoil;
                const float inrF = inr * invFC;
                const float yp   = y + inrF;                 // parallel w/ lg2
                const float sv   = SLZ * CinvFC;
                const float oms  = 1.0f - sv;
                const float sw   = fast_ex2(BETA * fast_lg2(y));
                const float recharge = inr * sw;
                const float y1 = fmaf(-inrF, sw, yp);
                const float excess = fmaxf(y1 - 1.0f, 0.0f) * FC;
                const float y2 = fminf(y1, 1.0f);
                const float y3 = fmaf(y2, oms, sv);
                const float cap = SLZ * fmaxf(fmaf(-Cpar, y1, Cpar), 0.0f);
                SLZ -= cap;
                const float ef  = fast_ex2(fmaf(fast_lg2(y3), BETAET, bLP));
                const float PEF = PE * invFC;
                const float Kfl = fmaxf(y3 - PEF, epsF);
                y = fmaxf(fmaf(-PEF, ef, y3), Kfl);

                // response
                const float SUZ1 = SUZ + recharge + excess;
                const float SUZ2 = fmaxf(SUZ1 - PERC, 0.0f);
                const float PERCv = SUZ1 - SUZ2;
                const float tq  = fmaxf(SUZ2 - UZL, 0.0f);
                const float Q0  = K0 * tq;
                const float SUZ3 = fmaf(-K0, tq, SUZ2);
                const float Q1  = K1 * SUZ3;
                SUZ = oneK1 * SUZ3;
                const float SLZ1 = SLZ + PERCv;
                const float Q2  = K2 * SLZ1;
                SLZ = oneK2 * SLZ1;

                qb[j * 32] = Q0 + Q1 + Q2;      // STS, issue-only
            }
            bar64(pair + 1);                    // publish chunk c to helper
        }
    } else {
        // ================= HELPER WARP: conv + reduce + store =================
        const float* pb = ps + b * 288 + m;
        const float aa     = fmaxf(pb[256] * 2.9f, 0.0f) + 0.1f;
        const float theta  = fmaxf(pb[272] * 6.5f, 0.0f) + 0.5f;
        const float itheta = 1.0f / theta;

        float w[CH];
        float wsum = 0.0f;
#pragma unroll
        for (int k = 0; k < 15; ++k) {
            const float tk = (float)k + 0.5f;
            w[k] = expf((aa - 1.0f) * logf(tk) - tk * itheta);
            wsum += w[k];
        }
        const float iws = 1.0f / wsum;
#pragma unroll
        for (int k = 0; k < 15; ++k) w[k] *= iws;
        w[15] = 0.0f;

        float q[CH];
#pragma unroll
        for (int k = 0; k < CH; ++k) q[k] = 0.0f;

        const int tt = lane & 15;
        const int rdoff = (lane >> 4) * CSTR + tt * 20;
        float* wr = &red[pair][cell * CSTR + m];

#pragma unroll 1
        for (int c = 0; c < NCHUNK; ++c) {
            bar64(pair + 1);                    // wait for chunk c
            const float* qb = &qbuf[c & 1][pair][0][lane];
#pragma unroll
            for (int j = 0; j < CH; ++j) {
                q[j] = qb[j * 32];              // LDS, conflict-free
                float a0 = 0.f, a1 = 0.f, a2 = 0.f, a3 = 0.f;
#pragma unroll
                for (int k = 0; k < CH; k += 4) {
                    a0 = fmaf(w[k + 0], q[(j - k - 0) & 15], a0);
                    a1 = fmaf(w[k + 1], q[(j - k - 1) & 15], a1);
                    a2 = fmaf(w[k + 2], q[(j - k - 2) & 15], a2);
                    a3 = fmaf(w[k + 3], q[(j - k - 3) & 15], a3);
                }
                wr[j * 20] = (a0 + a1) + (a2 + a3);
            }
            __syncwarp();
            {
                const float4* rp = (const float4*)&red[pair][rdoff];
                const float4 v0 = rp[0], v1 = rp[1], v2 = rp[2], v3 = rp[3];
                const float s01 = ((v0.x + v0.y) + (v0.z + v0.w))
                                + ((v1.x + v1.y) + (v1.z + v1.w));
                const float s23 = ((v2.x + v2.y) + (v2.z + v2.w))
                                + ((v3.x + v3.y) + (v3.z + v3.w));
                out[(c * CH + tt) * NB + (b0 + (lane >> 4))] = (s01 + s23) * 0.0625f;
            }
            __syncwarp();
        }
    }
}

extern "C" void kernel_launch(void* const* d_in, const int* in_sizes, int n_in,
                              void* d_out, int out_size)
{
    const float* x  = (const float*)d_in[0];
    const float* ps = (const float*)d_in[1];
    if (n_in >= 2 && in_sizes[0] == NB * 288) {  // swapped order
        x  = (const float*)d_in[1];
        ps = (const float*)d_in[0];
    }
    float* out = (float*)d_out;
    hbv_kernel<<<NBLK, NTH>>>(x, ps, out);
}

// round 16
// speedup vs baseline: 3.0695x; 1.1230x over previous
#include <cuda_runtime.h>

#define T_STEPS 2000
#define NB      1024
#define NMUL    16
#define NTH     128   // 4 warps -> SMSPs 0..3 (1 warp/SMSP: proven optimal)
#define NBLK    128   // 128*128 = 16384 threads = NB*NMUL
#define CH      16    // steps per chunk (= conv ring size = unroll)
#define NCHUNK  (T_STEPS / CH)   // 125, exact
#define PF      4     // forcing prefetch depth
#define CSTR    336   // cell stride in red[] floats: %32==16 -> conflict-free

__device__ __forceinline__ float fast_lg2(float a) {
    float r;
    asm("lg2.approx.f32 %0, %1;" : "=f"(r) : "f"(a));
    return r;
}
__device__ __forceinline__ float fast_ex2(float a) {
    float r;
    asm("ex2.approx.f32 %0, %1;" : "=f"(r) : "f"(a));
    return r;
}

__global__ void __launch_bounds__(NTH, 1)
hbv_kernel(const float* __restrict__ x,      // (T, B, 3)
           const float* __restrict__ ps,     // (B, 288)
           float* __restrict__ out)          // (T, B)
{
    // double-buffered transpose stage: [buf][warp][cell*CSTR + t*20 + m]
    __shared__ float red[2][4][2 * CSTR];

    const int m    = threadIdx.x & (NMUL - 1);
    const int w_id = threadIdx.x >> 5;
    const int lane = threadIdx.x & 31;
    const int cell = lane >> 4;
    const int tt   = lane & 15;

    const int gwarp = blockIdx.x * 4 + w_id;
    const int b     = gwarp * 2 + cell;
    const int b0    = gwarp * 2;

    const float* pb = ps + b * 288 + m;

    // --- physical parameters (parRT, parAC unused by the model) ---
    const float BETA   = 1.0f   + pb[0*16]  * 5.0f;
    const float FC     = 50.0f  + pb[1*16]  * 950.0f;
    const float K0     = 0.05f  + pb[2*16]  * 0.85f;
    const float K1     = 0.01f  + pb[3*16]  * 0.49f;
    const float K2     = 0.001f + pb[4*16]  * 0.199f;
    const float LP     = 0.2f   + pb[5*16]  * 0.8f;
    const float PERC   =          pb[6*16]  * 10.0f;
    const float UZL    =          pb[7*16]  * 100.0f;
    const float TT     = -2.5f  + pb[8*16]  * 5.0f;
    const float CFMAX  = 0.5f   + pb[9*16]  * 9.5f;
    const float CFR    =          pb[10*16] * 0.1f;
    const float CWH    =          pb[11*16] * 0.2f;
    const float BETAET = 0.3f   + pb[12*16] * 4.7f;
    const float Cpar   =          pb[13*16];

    const float invFC    = 1.0f / FC;
    const float bLP      = BETAET * fast_lg2(1.0f / LP);
    const float epsF     = 1e-5f * invFC;
    const float CFRCFMAX = CFR * CFMAX;
    const float CinvFC   = Cpar * invFC;
    const float oneK1    = 1.0f - K1;
    const float oneK2    = 1.0f - K2;
    const float opCWH    = 1.0f + CWH;

    // --- routing weights (gammaln prefactor cancels under normalization) ---
    const float aa     = fmaxf(pb[256] * 2.9f, 0.0f) + 0.1f;
    const float theta  = fmaxf(pb[272] * 6.5f, 0.0f) + 0.5f;
    const float itheta = 1.0f / theta;

    float w[CH];
    float wsum = 0.0f;
#pragma unroll
    for (int k = 0; k < 15; ++k) {
        const float tk = (float)k + 0.5f;
        w[k] = expf((aa - 1.0f) * logf(tk) - tk * itheta);
        wsum += w[k];
    }
    const float iws = 1.0f / wsum;
#pragma unroll
    for (int k = 0; k < 15; ++k) w[k] *= iws;
    w[15] = 0.0f;                         // dummy tap so ring period == unroll

    // --- state (y = SM/FC normalized) ---
    float SP  = 1e-5f, MW = 1e-5f, SUZ = 1e-5f, SLZ = 1e-5f;
    float y   = epsF;

    float q[CH];
#pragma unroll
    for (int k = 0; k < CH; ++k) q[k] = 0.0f;

    // --- forcing prefetch ring ---
    const float* xr = x + (size_t)b * 3;
    float Pf[PF], Tf[PF], Ef[PF];
#pragma unroll
    for (int k = 0; k < PF; ++k) {
        const float* xp = xr + (size_t)k * (NB * 3);
        Pf[k] = __ldg(xp + 0);
        Tf[k] = __ldg(xp + 1);
        Ef[k] = __ldg(xp + 2);
    }

    const int rdoff = (lane >> 4) * CSTR + tt * 20;

    // one HBV body step; returns Qsim for step s
    auto do_step = [&](int s) -> float {
        const int s4 = s & (PF - 1);
        const float Pm = Pf[s4], Tc = Tf[s4], PE = Ef[s4];
        {
            const int tn = (s + PF < T_STEPS) ? (s + PF) : (T_STEPS - 1);
            const float* xp = xr + (size_t)tn * (NB * 3);
            Pf[s4] = __ldg(xp + 0);
            Tf[s4] = __ldg(xp + 1);
            Ef[s4] = __ldg(xp + 2);
        }
        // --- snow: melt/refreeze mutually exclusive (m0>0 => snow==0,
        //     r0>0 => melt==0), so both come straight from PREVIOUS state:
        const float rain = (Tc >= TT) ? Pm : 0.0f;
        const float snow = Pm - rain;
        const float m0 = fmaxf(CFMAX * (Tc - TT), 0.0f);
        const float r0 = fmaxf(CFRCFMAX * (TT - Tc), 0.0f);
        const float melt     = fminf(m0, SP);
        const float refreeze = fminf(r0, MW);
        const float d  = melt - refreeze;
        const float D  = fmaf(-CWH, SP, MW);
        const float E  = fmaf(-CWH, snow, D);
        const float g  = fmaf(opCWH, d, E);          // == MW2 - CWH*SP3 exactly
        const float tosoil = fmaxf(g, 0.0f);
        SP = SP + snow - melt + refreeze;
        MW = MW + d - tosoil;

        // --- soil (y = SM/FC in (0,1]) ---
        const float inr  = rain + tosoil;            // ready ~30, before sw
        const float inrF = inr * invFC;
        const float sv   = SLZ * CinvFC;             // NOTE: sv may exceed 1
        const float oms  = 1.0f - sv;
        const float yp   = y + inrF;
        const float sw   = fast_ex2(BETA * fast_lg2(y));
        const float recharge = inr * sw;             // off-chain
        const float y1 = fmaf(-inrF, sw, yp);        // y + inrF*(1-sw)
        const float excess = fmaxf(y1 - 1.0f, 0.0f) * FC;   // off-chain
        const float y2 = fminf(y1, 1.0f);
        const float y3 = fmaf(y2, oms, sv);          // valid for ANY sign of oms
        const float cap = SLZ * fmaxf(fmaf(-Cpar, y1, Cpar), 0.0f);
        SLZ -= cap;
        const float ef  = fast_ex2(fmaf(fast_lg2(y3), BETAET, bLP));
        const float PEF = PE * invFC;
        const float Kfl = fmaxf(y3 - PEF, epsF);     // exact ef<=1 clamp, off-chain
        y = fmaxf(fmaf(-PEF, ef, y3), Kfl);

        // --- response (side-chain) ---
        const float SUZ1 = SUZ + recharge + excess;
        const float SUZ2 = fmaxf(SUZ1 - PERC, 0.0f);
        const float PERCv = SUZ1 - SUZ2;
        const float tq  = fmaxf(SUZ2 - UZL, 0.0f);
        const float Q0  = K0 * tq;
        const float SUZ3 = fmaf(-K0, tq, SUZ2);
        const float Q1  = K1 * SUZ3;
        SUZ = oneK1 * SUZ3;
        const float SLZ1 = SLZ + PERCv;
        const float Q2  = K2 * SLZ1;
        SLZ = oneK2 * SLZ1;
        return Q0 + Q1 + Q2;
    };

    float Qprev;

    auto do_conv = [&](int i, float* wr) {
        q[i] = Qprev;
        float a0 = 0.f, a1 = 0.f, a2 = 0.f, a3 = 0.f;
#pragma unroll
        for (int k = 0; k < CH; k += 4) {
            a0 = fmaf(w[k + 0], q[(i - k - 0) & 15], a0);
            a1 = fmaf(w[k + 1], q[(i - k - 1) & 15], a1);
            a2 = fmaf(w[k + 2], q[(i - k - 2) & 15], a2);
            a3 = fmaf(w[k + 3], q[(i - k - 3) & 15], a3);
        }
        wr[i * 20] = (a0 + a1) + (a2 + a3);
    };

    auto do_reduce = [&](int buf, int c) {
        const float4* rp = (const float4*)&red[buf][w_id][rdoff];
        const float4 v0 = rp[0], v1 = rp[1], v2 = rp[2], v3 = rp[3];
        const float s01 = ((v0.x + v0.y) + (v0.z + v0.w))
                        + ((v1.x + v1.y) + (v1.z + v1.w));
        const float s23 = ((v2.x + v2.y) + (v2.z + v2.w))
                        + ((v3.x + v3.y) + (v3.z + v3.w));
        out[(c * CH + tt) * NB + (b0 + (lane >> 4))] = (s01 + s23) * 0.0625f;
    };

    Qprev = do_step(0);

#pragma unroll 1
    for (int c = 0; c < NCHUNK - 1; ++c) {
        const int buf = c & 1;
        float* wr = &red[buf][w_id][cell * CSTR + m];
#pragma unroll
        for (int i = 0; i < CH; ++i) {
            do_conv(i, wr);
            Qprev = do_step(c * CH + 1 + i);
        }
        __syncwarp();
        do_reduce(buf, c);
    }

    {
        const int c = NCHUNK - 1;
        const int buf = c & 1;
        float* wr = &red[buf][w_id][cell * CSTR + m];
#pragma unroll
        for (int i = 0; i < CH - 1; ++i) {
            do_conv(i, wr);
            Qprev = do_step(c * CH + 1 + i);
        }
        do_conv(CH - 1, wr);
        __syncwarp();
        do_reduce(buf, c);
    }
}

extern "C" void kernel_launch(void* const* d_in, const int* in_sizes, int n_in,
                              void* d_out, int out_size)
{
    const float* x  = (const float*)d_in[0];
    const float* ps = (const float*)d_in[1];
    if (n_in >= 2 && in_sizes[0] == NB * 288) {  // swapped order
        x  = (const float*)d_in[1];
        ps = (const float*)d_in[0];
    }
    float* out = (float*)d_out;
    hbv_kernel<<<NBLK, NTH>>>(x, ps, out);
}

// round 17
// speedup vs baseline: 3.2135x; 1.0469x over previous
#include <cuda_runtime.h>

#define T_STEPS 2000
#define NB      1024
#define NMUL    16
#define NTH     128   // 4 warps -> SMSPs 0..3 (1 warp/SMSP: proven optimal)
#define NBLK    128   // 128*128 = 16384 threads = NB*NMUL
#define CH      16    // steps per chunk (= conv ring size = unroll)
#define NCHUNK  (T_STEPS / CH)   // 125, exact
#define PF      4     // forcing prefetch depth (ring fed by LDS now)
#define CSTR    336   // red[] cell stride: %32==16 -> conflict-free

__device__ __forceinline__ float fast_lg2(float a) {
    float r;
    asm("lg2.approx.f32 %0, %1;" : "=f"(r) : "f"(a));
    return r;
}
__device__ __forceinline__ float fast_ex2(float a) {
    float r;
    asm("ex2.approx.f32 %0, %1;" : "=f"(r) : "f"(a));
    return r;
}

__global__ void __launch_bounds__(NTH, 1)
hbv_kernel(const float* __restrict__ x,      // (T, B, 3)
           const float* __restrict__ ps,     // (B, 288)
           float* __restrict__ out)          // (T, B)
{
    // transpose stage for the m-reduction (double-buffered)
    __shared__ float red[2][4][2 * CSTR];
    // forcing stage: [buf][warp][j*6 + cell*3 + comp], chunk k lives in buf k&1
    __shared__ float xstage[2][4][CH * 6];

    const int m    = threadIdx.x & (NMUL - 1);
    const int w_id = threadIdx.x >> 5;
    const int lane = threadIdx.x & 31;
    const int cell = lane >> 4;
    const int tt   = lane & 15;
    const int c3   = cell * 3;

    const int gwarp = blockIdx.x * 4 + w_id;
    const int b     = gwarp * 2 + cell;
    const int b0    = gwarp * 2;

    const float* pb = ps + b * 288 + m;

    // --- physical parameters (parRT, parAC unused by the model) ---
    const float BETA   = 1.0f   + pb[0*16]  * 5.0f;
    const float FC     = 50.0f  + pb[1*16]  * 950.0f;
    const float K0     = 0.05f  + pb[2*16]  * 0.85f;
    const float K1     = 0.01f  + pb[3*16]  * 0.49f;
    const float K2     = 0.001f + pb[4*16]  * 0.199f;
    const float LP     = 0.2f   + pb[5*16]  * 0.8f;
    const float PERC   =          pb[6*16]  * 10.0f;
    const float UZL    =          pb[7*16]  * 100.0f;
    const float TT     = -2.5f  + pb[8*16]  * 5.0f;
    const float CFMAX  = 0.5f   + pb[9*16]  * 9.5f;
    const float CFR    =          pb[10*16] * 0.1f;
    const float CWH    =          pb[11*16] * 0.2f;
    const float BETAET = 0.3f   + pb[12*16] * 4.7f;
    const float Cpar   =          pb[13*16];

    const float invFC    = 1.0f / FC;
    const float bLP      = BETAET * fast_lg2(1.0f / LP);
    const float epsF     = 1e-5f * invFC;
    const float CFRCFMAX = CFR * CFMAX;
    const float CinvFC   = Cpar * invFC;
    const float oneK1    = 1.0f - K1;
    const float oneK2    = 1.0f - K2;
    const float opCWH    = 1.0f + CWH;

    // --- routing weights (gammaln prefactor cancels under normalization) ---
    const float aa     = fmaxf(pb[256] * 2.9f, 0.0f) + 0.1f;
    const float theta  = fmaxf(pb[272] * 6.5f, 0.0f) + 0.5f;
    const float itheta = 1.0f / theta;

    float w[CH];
    float wsum = 0.0f;
#pragma unroll
    for (int k = 0; k < 15; ++k) {
        const float tk = (float)k + 0.5f;
        w[k] = expf((aa - 1.0f) * logf(tk) - tk * itheta);
        wsum += w[k];
    }
    const float iws = 1.0f / wsum;
#pragma unroll
    for (int k = 0; k < 15; ++k) w[k] *= iws;
    w[15] = 0.0f;

    // --- state (y = SM/FC normalized) ---
    float SP  = 1e-5f, MW = 1e-5f, SUZ = 1e-5f, SLZ = 1e-5f;
    float y   = epsF;

    float q[CH];
#pragma unroll
    for (int k = 0; k < CH; ++k) q[k] = 0.0f;

    // --- cooperative forcing loader: 3 floats per lane per chunk ---
    const int i0 = lane * 3;
    const int j0 = i0 / 6,       r0c = i0 % 6;
    const int j1 = (i0 + 1) / 6, r1c = (i0 + 1) % 6;
    const int j2 = (i0 + 2) / 6, r2c = (i0 + 2) % 6;
    const float* xg0 = x + (size_t)b0 * 3 + r0c + (size_t)j0 * (NB * 3);
    const float* xg1 = x + (size_t)b0 * 3 + r1c + (size_t)j1 * (NB * 3);
    const float* xg2 = x + (size_t)b0 * 3 + r2c + (size_t)j2 * (NB * 3);
    const size_t CHOFF = (size_t)CH * NB * 3;

    float* xw0 = &xstage[0][w_id][0];
    float* xw1 = &xstage[1][w_id][0];

    // chunk 0 -> buf0 directly; chunk 1 -> held registers
    float rg0 = __ldg(xg0), rg1 = __ldg(xg1), rg2 = __ldg(xg2);
    xw0[j0 * 6 + r0c] = rg0;
    xw0[j1 * 6 + r1c] = rg1;
    xw0[j2 * 6 + r2c] = rg2;
    rg0 = __ldg(xg0 + CHOFF);
    rg1 = __ldg(xg1 + CHOFF);
    rg2 = __ldg(xg2 + CHOFF);
    __syncwarp();

    // ring init from chunk 0, slots 0..PF-1
    float Pf[PF], Tf[PF], Ef[PF];
#pragma unroll
    for (int k = 0; k < PF; ++k) {
        Pf[k] = xw0[k * 6 + c3 + 0];
        Tf[k] = xw0[k * 6 + c3 + 1];
        Ef[k] = xw0[k * 6 + c3 + 2];
    }

    const int rdoff = (lane >> 4) * CSTR + tt * 20;

    // one HBV body step; jj = step index within current chunk frame (0..16)
    auto do_step = [&](int jj, const float* curb, const float* nxtb) -> float {
        const int s4 = jj & (PF - 1);
        const float Pm = Pf[s4], Tc = Tf[s4], PE = Ef[s4];
        // refill slot for step jj+PF via LDS (29 cyc; consumed 4 steps later)
        {
            const float* src  = (jj < CH - PF) ? curb : nxtb;
            const int   slot  = (jj < CH - PF) ? (jj + PF) : (jj + PF - CH);
            Pf[s4] = src[slot * 6 + c3 + 0];
            Tf[s4] = src[slot * 6 + c3 + 1];
            Ef[s4] = src[slot * 6 + c3 + 2];
        }
        // --- snow: melt/refreeze mutually exclusive -> both from PREVIOUS state
        const float rain = (Tc >= TT) ? Pm : 0.0f;
        const float snow = Pm - rain;
        const float m0 = fmaxf(CFMAX * (Tc - TT), 0.0f);
        const float r0 = fmaxf(CFRCFMAX * (TT - Tc), 0.0f);
        const float melt     = fminf(m0, SP);
        const float refreeze = fminf(r0, MW);
        const float d  = melt - refreeze;
        const float D  = fmaf(-CWH, SP, MW);
        const float E  = fmaf(-CWH, snow, D);
        const float g  = fmaf(opCWH, d, E);          // == MW2 - CWH*SP3 exactly
        const float tosoil = fmaxf(g, 0.0f);
        SP = SP + snow - melt + refreeze;
        MW = MW + d - tosoil;

        // --- soil (y = SM/FC in (0,1]) ---
        const float inr  = rain + tosoil;
        const float inrF = inr * invFC;
        const float sv   = SLZ * CinvFC;             // may exceed 1
        const float oms  = 1.0f - sv;
        const float yp   = y + inrF;
        const float sw   = fast_ex2(BETA * fast_lg2(y));
        const float recharge = inr * sw;             // off-chain
        const float y1 = fmaf(-inrF, sw, yp);
        const float excess = fmaxf(y1 - 1.0f, 0.0f) * FC;   // off-chain
        const float y2 = fminf(y1, 1.0f);
        const float y3 = fmaf(y2, oms, sv);          // sign-safe capillary fuse
        const float cap = SLZ * fmaxf(fmaf(-Cpar, y1, Cpar), 0.0f);
        SLZ -= cap;
        const float ef  = fast_ex2(fmaf(fast_lg2(y3), BETAET, bLP));
        const float PEF = PE * invFC;
        const float Kfl = fmaxf(y3 - PEF, epsF);     // exact ef<=1 clamp, off-chain
        y = fmaxf(fmaf(-PEF, ef, y3), Kfl);

        // --- response (side-chain) ---
        const float SUZ1 = SUZ + recharge + excess;
        const float SUZ2 = fmaxf(SUZ1 - PERC, 0.0f);
        const float PERCv = SUZ1 - SUZ2;
        const float tq  = fmaxf(SUZ2 - UZL, 0.0f);
        const float Q0  = K0 * tq;
        const float SUZ3 = fmaf(-K0, tq, SUZ2);
        const float Q1  = K1 * SUZ3;
        SUZ = oneK1 * SUZ3;
        const float SLZ1 = SLZ + PERCv;
        const float Q2  = K2 * SLZ1;
        SLZ = oneK2 * SLZ1;
        return Q0 + Q1 + Q2;
    };

    float Qprev;

    auto do_conv = [&](int i, float* wr) {
        q[i] = Qprev;
        float a0 = 0.f, a1 = 0.f, a2 = 0.f, a3 = 0.f;
#pragma unroll
        for (int k = 0; k < CH; k += 4) {
            a0 = fmaf(w[k + 0], q[(i - k - 0) & 15], a0);
            a1 = fmaf(w[k + 1], q[(i - k - 1) & 15], a1);
            a2 = fmaf(w[k + 2], q[(i - k - 2) & 15], a2);
            a3 = fmaf(w[k + 3], q[(i - k - 3) & 15], a3);
        }
        wr[i * 20] = (a0 + a1) + (a2 + a3);
    };

    auto do_reduce = [&](int buf, int c) {
        const float4* rp = (const float4*)&red[buf][w_id][rdoff];
        const float4 v0 = rp[0], v1 = rp[1], v2 = rp[2], v3 = rp[3];
        const float s01 = ((v0.x + v0.y) + (v0.z + v0.w))
                        + ((v1.x + v1.y) + (v1.z + v1.w));
        const float s23 = ((v2.x + v2.y) + (v2.z + v2.w))
                        + ((v3.x + v3.y) + (v3.z + v3.w));
        out[(c * CH + tt) * NB + (b0 + (lane >> 4))] = (s01 + s23) * 0.0625f;
    };

    // peeled step 0 (chunk 0 frame: curb = buf0, nxtb unused for jj=0)
    Qprev = do_step(0, xw0, xw1);

#pragma unroll 1
    for (int c = 0; c < NCHUNK - 1; ++c) {
        const int buf = c & 1;
        float* curb = buf ? xw1 : xw0;
        float* nxtb = buf ? xw0 : xw1;

        // head: publish chunk c+1 (regs -> nxtb), then fetch chunk c+2
        nxtb[j0 * 6 + r0c] = rg0;
        nxtb[j1 * 6 + r1c] = rg1;
        nxtb[j2 * 6 + r2c] = rg2;
        __syncwarp();
        {
            const int cc = (c + 2 < NCHUNK) ? (c + 2) : (NCHUNK - 1);
            const size_t off = (size_t)cc * CHOFF;
            rg0 = __ldg(xg0 + off);
            rg1 = __ldg(xg1 + off);
            rg2 = __ldg(xg2 + off);
        }

        float* wr = &red[buf][w_id][cell * CSTR + m];
#pragma unroll
        for (int i = 0; i < CH; ++i) {
            do_conv(i, wr);
            Qprev = do_step(1 + i, curb, nxtb);   // steps c*16+1 .. c*16+16
        }
        __syncwarp();
        do_reduce(buf, c);
    }

    // last chunk (c = 124): 15 bodies + final conv-only
    {
        const int c = NCHUNK - 1;
        const int buf = c & 1;
        float* curb = buf ? xw1 : xw0;
        float* nxtb = buf ? xw0 : xw1;
        nxtb[j0 * 6 + r0c] = rg0;     // duplicate data; refills from it are
        nxtb[j1 * 6 + r1c] = rg1;     // never consumed (target steps >= 2000)
        nxtb[j2 * 6 + r2c] = rg2;
        __syncwarp();

        float* wr = &red[buf][w_id][cell * CSTR + m];
#pragma unroll
        for (int i = 0; i < CH - 1; ++i) {
            do_conv(i, wr);
            Qprev = do_step(1 + i, curb, nxtb);   // up to step 1999
        }
        do_conv(CH - 1, wr);
        __syncwarp();
        do_reduce(buf, c);
    }
}

extern "C" void kernel_launch(void* const* d_in, const int* in_sizes, int n_in,
                              void* d_out, int out_size)
{
    const float* x  = (const float*)d_in[0];
    const float* ps = (const float*)d_in[1];
    if (n_in >= 2 && in_sizes[0] == NB * 288) {  // swapped order
        x  = (const float*)d_in[1];
        ps = (const float*)d_in[0];
    }
    float* out = (float*)d_out;
    hbv_kernel<<<NBLK, NTH>>>(x, ps, out);
}